// round 15
// baseline (speedup 1.0000x reference)
#include <cuda_runtime.h>
#include <math.h>

#define FULLMASK 0xffffffffu
#define EPS_REC 1e-4f

__device__ float g_C[361];     // eps * (w1 w1^T)^{-1}          (19x19)
__device__ float g_C2[361];    // 1.02*eps * W12 (W12^T W12)^-2 W12^T (19x19)
__device__ float g_W12[304];   // w1 * w2                        (19x16)
__device__ float g_W123[76];   // w1 * w2 * w3                   (19x4)

// ---------------------------------------------------------------------------
// COLD one-sided Jacobi fallback (noinline; spills acceptable).
// ---------------------------------------------------------------------------
template<int N>
__device__ __noinline__ void jacobi_onesided(float (&g)[20], float (&v)[20],
                                             int lane, int max_sweeps)
{
    constexpr int M = N - 1;
    #pragma unroll
    for (int k = 0; k < N; ++k) v[k] = (lane == k) ? 1.0f : 0.0f;

    for (int sweep = 0; sweep < max_sweeps; ++sweep) {
        bool anyrot = false;
        for (int r = 0; r < M; ++r) {
            int partner;
            if (lane >= N)      partner = lane;
            else if (lane == M) partner = r;
            else if (lane == r) partner = M;
            else                partner = ((2 * r - lane) % M + M) % M;

            float pg[N];
            float a0 = 0.f, a1 = 0.f, d0 = 0.f, d1 = 0.f;
            #pragma unroll
            for (int k = 0; k < N; ++k) {
                pg[k] = __shfl_sync(FULLMASK, g[k], partner);
                if (k & 1) { a1 = fmaf(g[k], g[k], a1); d1 = fmaf(g[k], pg[k], d1); }
                else       { a0 = fmaf(g[k], g[k], a0); d0 = fmaf(g[k], pg[k], d0); }
            }
            float a = a0 + a1;
            float d = d0 + d1;
            float bb = __shfl_sync(FULLMASK, a, partner);
            bool  lower = lane < partner;
            float app = lower ? a  : bb;
            float aqq = lower ? bb : a;

            bool rot = (d * d > 1e-12f * app * aqq);
            anyrot |= rot;

            float dsafe = rot ? d : 1.0f;
            float tau = __fdividef(aqq - app, 2.0f * dsafe);
            float t   = __fdividef(copysignf(1.0f, tau),
                                   fabsf(tau) + __fsqrt_rn(fmaf(tau, tau, 1.0f)));
            float cc  = __frsqrt_rn(fmaf(t, t, 1.0f));
            float ss  = t * cc;
            if (!rot) { cc = 1.0f; ss = 0.0f; }
            float sl = lower ? -ss : ss;

            #pragma unroll
            for (int k = 0; k < N; ++k) {
                float pv = __shfl_sync(FULLMASK, v[k], partner);
                g[k] = fmaf(sl, pg[k], cc * g[k]);
                v[k] = fmaf(sl, pv,    cc * v[k]);
            }
        }
        if (!__any_sync(FULLMASK, anyrot)) break;
    }
}

// COLD: m += (eps - lambda_i) v_i v_i^T over deficient eigenpairs.
template<int N, int NREAL>
__device__ __noinline__ void reeig_correction(float (&m)[20], const float (&g)[20],
                                              const float (&v)[20], int lane)
{
    float lam = 0.f;
    #pragma unroll
    for (int k = 0; k < N; ++k) lam = fmaf(v[k], g[k], lam);

    bool defic = (lane < NREAL) && (lam < EPS_REC);
    unsigned mask = __ballot_sync(FULLMASK, defic);
    while (mask) {
        int i = __ffs(mask) - 1;
        mask &= mask - 1;
        float li   = __shfl_sync(FULLMASK, lam, i);
        float coef = EPS_REC - li;
        float vmy  = 0.f;
        float bv[N];
        #pragma unroll
        for (int k = 0; k < N; ++k) {
            bv[k] = __shfl_sync(FULLMASK, v[k], i);
            vmy   = (lane == k) ? bv[k] : vmy;
        }
        float cf = coef * vmy;
        #pragma unroll
        for (int k = 0; k < N; ++k) m[k] = fmaf(cf, bv[k], m[k]);
    }
}

// Vectorized dot of a 16B-aligned shared row with a register array.
template<int Q, int W>
__device__ __forceinline__ float dotv(const float* __restrict__ row,
                                      const float (&w)[W])
{
    const float4* r4 = (const float4*)row;
    float a0 = 0.f, a1 = 0.f, a2 = 0.f, a3 = 0.f;
    #pragma unroll
    for (int q = 0; q < Q; ++q) {
        float4 rv = r4[q];
        a0 = fmaf(rv.x, w[4 * q + 0], a0);
        a1 = fmaf(rv.y, w[4 * q + 1], a1);
        a2 = fmaf(rv.z, w[4 * q + 2], a2);
        a3 = fmaf(rv.w, w[4 * q + 3], a3);
    }
    return (a0 + a1) + (a2 + a3);
}

// COLD: single-matrix stage-1 GEMM M1 = w1^T X w1 (column `lane`).
__device__ __noinline__ void stage1_gemm(const float (*Sm)[20],
                                         const float (*sw1t)[20],
                                         int lane, float (&m)[20])
{
    int j = (lane < 19) ? lane : 0;
    float wc[20], t[20];
    #pragma unroll
    for (int q = 0; q < 5; ++q)
        *(float4*)&wc[4 * q] = *(const float4*)&sw1t[j][4 * q];
    #pragma unroll
    for (int i = 0; i < 19; ++i) t[i] = dotv<5>(Sm[i], wc);
    t[19] = 0.f;
    #pragma unroll
    for (int i = 0; i < 19; ++i) {
        float acc = dotv<5>(sw1t[i], t);
        m[i] = (lane < 19) ? acc : 0.f;
    }
    m[19] = 0.f;
}

// Grouped Cholesky: two 16x16 per warp (g=lane>>4, j=lane&15). Sticky ok.
__device__ __forceinline__ bool chol16_grouped(const float (&m)[16], int lane)
{
    int base = lane & 16;
    int j    = lane & 15;
    float c[16];
    #pragma unroll
    for (int k = 0; k < 16; ++k) c[k] = (j == k) ? (m[k] - EPS_REC) : m[k];

    bool ok = true;
    #pragma unroll
    for (int k = 0; k < 16; ++k) {
        float ckk = __shfl_sync(FULLMASK, c[k], base + k);
        ok = ok && (ckk > 1e-12f);
        float gmul = c[k] * __fdividef(1.0f, fmaxf(ckk, 1e-12f));
        #pragma unroll
        for (int i = k + 1; i < 16; ++i) {
            float pk = __shfl_sync(FULLMASK, c[i], base + k);
            c[i] = fmaf(-pk, gmul, c[i]);
        }
    }
    return ok;
}

// Grouped 4x4 one-sided Jacobi: 8 independent 4-lane groups per warp.
__device__ __forceinline__ void jacobi4g(float (&g)[4], float (&v)[4],
                                         int lane, int max_sweeps)
{
    int j = lane & 3, base = lane & ~3;
    #pragma unroll
    for (int k = 0; k < 4; ++k) v[k] = (j == k) ? 1.0f : 0.0f;

    for (int sweep = 0; sweep < max_sweeps; ++sweep) {
        bool anyrot = false;
        #pragma unroll
        for (int r = 0; r < 3; ++r) {
            int p = (j == 3) ? r : (j == r) ? 3 : ((2 * r - j) % 3 + 3) % 3;
            int partner = base + p;

            float pg[4];
            float a = 0.f, d = 0.f;
            #pragma unroll
            for (int k = 0; k < 4; ++k) {
                pg[k] = __shfl_sync(FULLMASK, g[k], partner);
                a = fmaf(g[k], g[k], a);
                d = fmaf(g[k], pg[k], d);
            }
            float bb = __shfl_sync(FULLMASK, a, partner);
            bool  lower = j < p;
            float app = lower ? a  : bb;
            float aqq = lower ? bb : a;

            bool rot = (d * d > 1e-12f * app * aqq);
            anyrot |= rot;

            float dsafe = rot ? d : 1.0f;
            float tau = __fdividef(aqq - app, 2.0f * dsafe);
            float t   = __fdividef(copysignf(1.0f, tau),
                                   fabsf(tau) + __fsqrt_rn(fmaf(tau, tau, 1.0f)));
            float cc  = __frsqrt_rn(fmaf(t, t, 1.0f));
            float ss  = t * cc;
            if (!rot) { cc = 1.0f; ss = 0.0f; }
            float sl = lower ? -ss : ss;

            #pragma unroll
            for (int k = 0; k < 4; ++k) {
                float pv = __shfl_sync(FULLMASK, v[k], partner);
                g[k] = fmaf(sl, pg[k], cc * g[k]);
                v[k] = fmaf(sl, pv,    cc * v[k]);
            }
        }
        if (!__any_sync(FULLMASK, anyrot)) break;
    }
}

// ---------------------------------------------------------------------------
// Precompute (1 warp):
//   C    = eps*(w1 w1^T)^{-1}
//   W12  = w1*w2,  W123 = W12*w3
//   C2   = 1.02*eps * W12 G^{-2} W12^T,  G = W12^T W12
// X >= C  ==> M1 >= eps I (ReEig1 identity);  X >= C2 ==> M2 >= eps I.
// Any dodgy factorization => the corresponding cone := 1e30*I (always cold).
// ---------------------------------------------------------------------------
__global__ void spd_precompute(const float* __restrict__ w1,
                               const float* __restrict__ w2,
                               const float* __restrict__ w3)
{
    __shared__ float s1[361], s2[304], s3[64], s12[304], sK[304];
    int lane = threadIdx.x & 31;
    for (int i = lane; i < 361; i += 32) s1[i] = w1[i];
    for (int i = lane; i < 304; i += 32) s2[i] = w2[i];
    if (lane < 32) for (int i = lane; i < 64; i += 32) s3[i] = w3[i];
    __syncwarp();

    int j = (lane < 19) ? lane : 0;

    // ===== C = eps*(w1 w1^T)^{-1} =====
    bool ok;
    {
        float r[19], c[19];
        #pragma unroll
        for (int k = 0; k < 19; ++k) r[k] = s1[j * 19 + k];
        #pragma unroll
        for (int i = 0; i < 19; ++i) {
            float acc = 0.f;
            #pragma unroll
            for (int k = 0; k < 19; ++k) acc = fmaf(s1[i * 19 + k], r[k], acc);
            c[i] = acc;
        }
        ok = true;
        float invD[19], myid = 1.0f;
        #pragma unroll
        for (int k = 0; k < 19; ++k) {
            float dk = __shfl_sync(FULLMASK, c[k], k);
            ok = ok && (dk > 1e-20f);
            float id = __fdividef(1.0f, fmaxf(dk, 1e-20f));
            invD[k] = id;
            if (k == j) myid = id;
            float gmul = (j > k) ? c[k] * id : 0.0f;
            #pragma unroll
            for (int i = k + 1; i < 19; ++i) {
                float pk = __shfl_sync(FULLMASK, c[i], k);
                c[i] = fmaf(-pk, gmul, c[i]);
            }
        }
        float l[19];
        #pragma unroll
        for (int i = 0; i < 19; ++i)
            l[i] = (i > j) ? c[i] * myid : ((i == j) ? 1.0f : 0.0f);
        float u[19];
        #pragma unroll
        for (int i = 0; i < 19; ++i) u[i] = (i == j) ? 1.0f : 0.0f;
        #pragma unroll
        for (int i = 1; i < 19; ++i) {
            float acc = 0.f;
            #pragma unroll
            for (int k = 0; k < i; ++k) {
                float Lik = __shfl_sync(FULLMASK, l[i], k);
                acc = fmaf(Lik, u[k], acc);
            }
            u[i] -= acc;
        }
        float z[19];
        #pragma unroll
        for (int m = 0; m < 19; ++m) z[m] = EPS_REC * invD[m] * u[m];
        #pragma unroll
        for (int a = 0; a < 19; ++a) {
            float acc = 0.f;
            #pragma unroll
            for (int m = 0; m < 19; ++m) {
                float Uma = __shfl_sync(FULLMASK, u[m], a);
                acc = fmaf(Uma, z[m], acc);
            }
            if (lane < 19) g_C[a * 19 + lane] = ok ? acc : ((a == lane) ? 1e30f : 0.0f);
        }
    }

    // ===== W12 = w1*w2 (col j16 per lane) =====
    int j16 = (lane < 16) ? lane : 0;
    float w12c[19];
    {
        float rc[19];
        #pragma unroll
        for (int k = 0; k < 19; ++k) rc[k] = s2[k * 16 + j16];
        #pragma unroll
        for (int i = 0; i < 19; ++i) {
            float acc = 0.f;
            #pragma unroll
            for (int k = 0; k < 19; ++k) acc = fmaf(s1[i * 19 + k], rc[k], acc);
            w12c[i] = acc;
            if (lane < 16) { g_W12[i * 16 + lane] = acc; s12[i * 16 + lane] = acc; }
        }
    }
    __syncwarp();

    // ===== G = W12^T W12 (16x16), LDL^T, H = G^{-1}, K = W12*H =====
    bool ok2 = ok;
    {
        float gcol[16];
        #pragma unroll
        for (int i = 0; i < 16; ++i) {
            float acc = 0.f;
            #pragma unroll
            for (int k = 0; k < 19; ++k) acc = fmaf(s12[k * 16 + i], w12c[k], acc);
            gcol[i] = acc;
        }
        float invD2[16], myid2 = 1.0f;
        #pragma unroll
        for (int k = 0; k < 16; ++k) {
            float dk = __shfl_sync(FULLMASK, gcol[k], k);
            ok2 = ok2 && (dk > 1e-20f);
            float id = __fdividef(1.0f, fmaxf(dk, 1e-20f));
            invD2[k] = id;
            if (k == j16) myid2 = id;
            float gmul = (j16 > k) ? gcol[k] * id : 0.0f;
            #pragma unroll
            for (int i = k + 1; i < 16; ++i) {
                float pk = __shfl_sync(FULLMASK, gcol[i], k);
                gcol[i] = fmaf(-pk, gmul, gcol[i]);
            }
        }
        float l2[16];
        #pragma unroll
        for (int i = 0; i < 16; ++i)
            l2[i] = (i > j16) ? gcol[i] * myid2 : ((i == j16) ? 1.0f : 0.0f);
        float u2[16];
        #pragma unroll
        for (int i = 0; i < 16; ++i) u2[i] = (i == j16) ? 1.0f : 0.0f;
        #pragma unroll
        for (int i = 1; i < 16; ++i) {
            float acc = 0.f;
            #pragma unroll
            for (int k = 0; k < i; ++k) {
                float Lik = __shfl_sync(FULLMASK, l2[i], k);
                acc = fmaf(Lik, u2[k], acc);
            }
            u2[i] -= acc;
        }
        float z2[16], hcol[16];
        #pragma unroll
        for (int m = 0; m < 16; ++m) z2[m] = invD2[m] * u2[m];
        #pragma unroll
        for (int a = 0; a < 16; ++a) {
            float acc = 0.f;
            #pragma unroll
            for (int m = 0; m < 16; ++m) {
                float Uma = __shfl_sync(FULLMASK, u2[m], a);
                acc = fmaf(Uma, z2[m], acc);
            }
            hcol[a] = acc;
        }
        // K col j16 = W12 * hcol
        #pragma unroll
        for (int i = 0; i < 19; ++i) {
            float acc = 0.f;
            #pragma unroll
            for (int m = 0; m < 16; ++m) acc = fmaf(s12[i * 16 + m], hcol[m], acc);
            if (lane < 16) sK[i * 16 + lane] = acc;
        }
    }
    __syncwarp();

    // ===== C2 = 1.02*eps * K K^T, column `lane` =====
    {
        int b = (lane < 19) ? lane : 0;
        float rb[16];
        #pragma unroll
        for (int m = 0; m < 16; ++m) rb[m] = sK[b * 16 + m];
        #pragma unroll
        for (int a = 0; a < 19; ++a) {
            float acc = 0.f;
            #pragma unroll
            for (int m = 0; m < 16; ++m) acc = fmaf(sK[a * 16 + m], rb[m], acc);
            if (lane < 19)
                g_C2[a * 19 + lane] = ok2 ? (1.02f * EPS_REC) * acc
                                          : ((a == lane) ? 1e30f : 0.0f);
        }
    }

    // ===== W123 = W12 * w3 (col c per lane<4) =====
    {
        int c4 = (lane < 4) ? lane : 0;
        float r3[16];
        #pragma unroll
        for (int m = 0; m < 16; ++m) r3[m] = s3[m * 4 + c4];
        #pragma unroll
        for (int i = 0; i < 19; ++i) {
            float acc = 0.f;
            #pragma unroll
            for (int m = 0; m < 16; ++m) acc = fmaf(s12[i * 16 + m], r3[m], acc);
            if (lane < 4) g_W123[i * 4 + lane] = acc;
        }
    }
}

// ---------------------------------------------------------------------------
// Main: 16 matrices / 256-thread block, 2 per warp.
// Dual chol19(X-C) -> ReEig1 identity?  Dual chol19(X-C2) -> ReEig2 identity?
// Both pass: skip Phase B entirely; Phase C = W123^T X W123.
// Otherwise: r12 path (Phase B GEMM + chol16 + cold fixes).
// Phase C is branch-uniform via zero-padded weight tables.
// ---------------------------------------------------------------------------
__global__ void __launch_bounds__(256, 4)
spd_net_kernel(const float* __restrict__ x,
               const float* __restrict__ w1,
               const float* __restrict__ w2,
               const float* __restrict__ w3,
               const float* __restrict__ fcw,
               float* __restrict__ out_logp,
               float* __restrict__ out_feat,
               int B)
{
    __shared__ __align__(16) float sw1t[19][20];
    __shared__ __align__(16) float sw2t[16][20];
    __shared__ __align__(16) float sw12t[16][20];
    __shared__ __align__(16) float sC[19][20];
    __shared__ __align__(16) float sC2[19][20];
    __shared__ __align__(16) float sw3t[4][20];     // w3 cols, zero-padded k>=16
    __shared__ __align__(16) float sW123[4][20];    // W123 cols, zero-padded k>=19
    __shared__ float sfc[32];
    __shared__ int   sc2[16];
    __shared__ __align__(16) float S[16][21][20];

    int tid = threadIdx.x;
    for (int idx = tid; idx < 19 * 20; idx += 256) {
        int i = idx / 20, k = idx % 20;
        sw1t[i][k] = (k < 19) ? w1[k * 19 + i] : 0.f;
        sC[i][k]   = (k < 19) ? g_C[i * 19 + k] : 0.f;
        sC2[i][k]  = (k < 19) ? g_C2[i * 19 + k] : 0.f;
    }
    for (int idx = tid; idx < 16 * 20; idx += 256) {
        int i = idx / 20, k = idx % 20;
        sw2t[i][k]  = (k < 19) ? w2[k * 16 + i] : 0.f;
        sw12t[i][k] = (k < 19) ? g_W12[k * 16 + i] : 0.f;
    }
    if (tid < 80) {
        int i = tid / 20, k = tid % 20;
        sw3t[i][k]  = (k < 16) ? w3[k * 4 + i] : 0.f;
        sW123[i][k] = (k < 19) ? g_W123[k * 4 + i] : 0.f;
    }
    if (tid < 32) sfc[tid] = fcw[tid];
    __syncthreads();

    int warp = tid >> 5, lane = tid & 31;
    int blockBase = blockIdx.x * 16;
    int qA = 2 * warp, qBm = qA + 1;
    int bA = blockBase + qA, bB = blockBase + qBm;
    float (*SmA)[20] = S[qA];
    float (*SmB)[20] = S[qBm];

    if (bA < B) {
        const float* xa = x + (size_t)bA * 361;
        for (int i = lane; i < 361; i += 32) SmA[i / 19][i % 19] = xa[i];
    }
    if (bB < B) {
        const float* xb = x + (size_t)bB * 361;
        for (int i = lane; i < 361; i += 32) SmB[i / 19][i % 19] = xb[i];
    }
    if (lane < 19) { SmA[lane][19] = 0.f; SmB[lane][19] = 0.f; }
    __syncwarp();

    int j19 = (lane < 19) ? lane : 0;

    // ======== Test 1: dual interleaved chol19 on (X - C) ========
    bool okA = true, okB = true;
    {
        float cA[19], cB[19];
        #pragma unroll
        for (int k = 0; k < 19; ++k) {
            float ck = sC[k][j19];
            cA[k] = SmA[k][j19] - ck;
            cB[k] = SmB[k][j19] - ck;
        }
        #pragma unroll
        for (int k = 0; k < 19; ++k) {
            float pA = __shfl_sync(FULLMASK, cA[k], k);
            float pB = __shfl_sync(FULLMASK, cB[k], k);
            okA = okA && (pA > 1e-12f);
            okB = okB && (pB > 1e-12f);
            float gA = cA[k] * __fdividef(1.0f, fmaxf(pA, 1e-12f));
            float gB = cB[k] * __fdividef(1.0f, fmaxf(pB, 1e-12f));
            #pragma unroll
            for (int i = k + 1; i < 19; ++i) {
                float fA = __shfl_sync(FULLMASK, cA[i], k);
                float fB = __shfl_sync(FULLMASK, cB[i], k);
                cA[i] = fmaf(-fA, gA, cA[i]);
                cB[i] = fmaf(-fB, gB, cB[i]);
            }
        }
    }

    // ======== Test 2: dual interleaved chol19 on (X - C2) ========
    bool c2A = true, c2B = true;
    {
        float cA[19], cB[19];
        #pragma unroll
        for (int k = 0; k < 19; ++k) {
            float ck = sC2[k][j19];
            cA[k] = SmA[k][j19] - ck;
            cB[k] = SmB[k][j19] - ck;
        }
        #pragma unroll
        for (int k = 0; k < 19; ++k) {
            float pA = __shfl_sync(FULLMASK, cA[k], k);
            float pB = __shfl_sync(FULLMASK, cB[k], k);
            c2A = c2A && (pA > 1e-12f);
            c2B = c2B && (pB > 1e-12f);
            float gA = cA[k] * __fdividef(1.0f, fmaxf(pA, 1e-12f));
            float gB = cB[k] * __fdividef(1.0f, fmaxf(pB, 1e-12f));
            #pragma unroll
            for (int i = k + 1; i < 19; ++i) {
                float fA = __shfl_sync(FULLMASK, cA[i], k);
                float fB = __shfl_sync(FULLMASK, cB[i], k);
                cA[i] = fmaf(-fA, gA, cA[i]);
                cB[i] = fmaf(-fB, gB, cB[i]);
            }
        }
    }
    c2A = c2A && okA;
    c2B = c2B && okB;

    // ======== Cold stage-1: compute M1, ReEig, overwrite X with Y1 ========
    bool badA = !okA && (bA < B);
    bool badB = !okB && (bB < B);
    if (badA || badB) {
        #pragma unroll 1
        for (int rr = 0; rr < 2; ++rr) {
            bool bad = rr ? badB : badA;
            if (bad) {
                float (*Sm)[20] = rr ? SmB : SmA;
                float m[20], g[20], v[20];
                stage1_gemm(Sm, sw1t, lane, m);
                #pragma unroll
                for (int k = 0; k < 20; ++k) g[k] = m[k];
                jacobi_onesided<20>(g, v, lane, 12);
                reeig_correction<20, 19>(m, g, v, lane);
                __syncwarp();
                if (lane < 19) {
                    #pragma unroll
                    for (int k = 0; k < 19; ++k) Sm[k][lane] = m[k];  // Y1
                }
            }
            __syncwarp();
        }
    }
    __syncwarp();

    // ======== Phase B (only if some matrix needs explicit M2) ========
    if (!(c2A && c2B)) {
        int gB2 = lane >> 4;
        int jB  = lane & 15;
        float (*SmP)[20] = S[2 * warp + gB2];
        bool myc2  = gB2 ? c2B : c2A;
        bool fastP = gB2 ? okB : okA;
        const float (*wt)[20] = fastP ? sw12t : sw2t;

        float m16[16];
        {
            float wc[20], t[20];
            #pragma unroll
            for (int q = 0; q < 5; ++q)
                *(float4*)&wc[4 * q] = *(const float4*)&wt[jB][4 * q];
            #pragma unroll
            for (int kk = 0; kk < 19; ++kk) t[kk] = dotv<5>(SmP[kk], wc);
            t[19] = 0.f;
            #pragma unroll
            for (int i = 0; i < 16; ++i) m16[i] = dotv<5>(wt[i], t);
        }

        bool okP = chol16_grouped(m16, lane);
        __syncwarp();                               // reads of rows 0-18 done
        if (!myc2) {
            #pragma unroll
            for (int k = 0; k < 16; ++k) SmP[k][jB] = m16[k];   // Y2 rows 0-15
        }
        __syncwarp();

        bool fixA = !__shfl_sync(FULLMASK, okP, 0)  && !c2A && (bA < B);
        bool fixB = !__shfl_sync(FULLMASK, okP, 16) && !c2B && (bB < B);
        if (fixA || fixB) {                          // COLD stage-2 fix
            #pragma unroll 1
            for (int rr = 0; rr < 2; ++rr) {
                bool fix = rr ? fixB : fixA;
                if (fix) {
                    int qq = 2 * warp + rr;
                    float mm[20], g[20], v[20];
                    #pragma unroll
                    for (int k = 0; k < 16; ++k)
                        mm[k] = (lane < 16) ? S[qq][k][lane] : 0.f;
                    #pragma unroll
                    for (int k = 16; k < 20; ++k) mm[k] = 0.f;
                    #pragma unroll
                    for (int k = 0; k < 20; ++k) g[k] = mm[k];
                    jacobi_onesided<16>(g, v, lane, 12);
                    reeig_correction<16, 16>(mm, g, v, lane);
                    __syncwarp();
                    if (lane < 16) {
                        #pragma unroll
                        for (int k = 0; k < 16; ++k) S[qq][k][lane] = mm[k];
                    }
                }
                __syncwarp();
            }
        }
    }

    if (lane == 0)  sc2[qA]  = c2A ? 1 : 0;
    if (lane == 16) sc2[qBm] = c2B ? 1 : 0;

    __syncthreads();                                // handoff to Phase C

    // ======== Phase C (warps 0-1 only): 8 matrices per warp ========
    if (warp >= 2) return;

    int jC = lane & 3;
    int gC = lane >> 2;
    int qC = warp * 8 + gC;
    int bC = blockBase + qC;
    float (*SmC)[20] = S[qC];

    // c2-passed: rows 0-18 = X, weights = W123. Else rows 0-15 = Y2,
    // weights = w3 zero-padded (zeros kill stale rows/cols).
    const float (*wsel)[20] = sc2[qC] ? sW123 : sw3t;

    float m4[4];
    {
        float wc[20], t[20];
        #pragma unroll
        for (int q = 0; q < 5; ++q)
            *(float4*)&wc[4 * q] = *(const float4*)&wsel[jC][4 * q];
        #pragma unroll
        for (int kk = 0; kk < 19; ++kk) t[kk] = dotv<5>(SmC[kk], wc);
        t[19] = 0.f;
        #pragma unroll
        for (int i = 0; i < 4; ++i) m4[i] = dotv<5>(wsel[i], t);
    }

    float g4[4], v4[4];
    #pragma unroll
    for (int k = 0; k < 4; ++k) g4[k] = m4[k];
    jacobi4g(g4, v4, lane, 8);

    float lam = 0.f;
    #pragma unroll
    for (int k = 0; k < 4; ++k) lam = fmaf(v4[k], g4[k], lam);
    float ll = logf(fmaxf(lam, 1e-30f));

    int baseC = lane & ~3;
    float c3[4] = {0.f, 0.f, 0.f, 0.f};
    #pragma unroll
    for (int mm = 0; mm < 4; ++mm) {
        float llm = __shfl_sync(FULLMASK, ll,    baseC + mm);
        float bv0 = __shfl_sync(FULLMASK, v4[0], baseC + mm);
        float bv1 = __shfl_sync(FULLMASK, v4[1], baseC + mm);
        float bv2 = __shfl_sync(FULLMASK, v4[2], baseC + mm);
        float bv3 = __shfl_sync(FULLMASK, v4[3], baseC + mm);
        float vmj = (jC == 0) ? bv0 : (jC == 1) ? bv1 : (jC == 2) ? bv2 : bv3;
        float cf  = llm * vmj;
        c3[0] = fmaf(cf, bv0, c3[0]);
        c3[1] = fmaf(cf, bv1, c3[1]);
        c3[2] = fmaf(cf, bv2, c3[2]);
        c3[3] = fmaf(cf, bv3, c3[3]);
    }

    bool inRange = (bC < B);

    if (out_feat && inRange) {
        #pragma unroll
        for (int i = 0; i < 4; ++i)
            out_feat[(size_t)bC * 16 + i * 4 + jC] = c3[i];
    }

    if (out_logp) {
        float p0 = 0.f, p1 = 0.f;
        #pragma unroll
        for (int i = 0; i < 4; ++i) {
            int f = i * 4 + jC;
            p0 = fmaf(c3[i], sfc[f * 2 + 0], p0);
            p1 = fmaf(c3[i], sfc[f * 2 + 1], p1);
        }
        p0 += __shfl_xor_sync(FULLMASK, p0, 1);
        p0 += __shfl_xor_sync(FULLMASK, p0, 2);
        p1 += __shfl_xor_sync(FULLMASK, p1, 1);
        p1 += __shfl_xor_sync(FULLMASK, p1, 2);
        if (inRange && jC == 0) {
            float mx  = fmaxf(p0, p1);
            float lse = mx + logf(expf(p0 - mx) + expf(p1 - mx));
            out_logp[(size_t)bC * 2 + 0] = p0 - lse;
            out_logp[(size_t)bC * 2 + 1] = p1 - lse;
        }
    }
}

extern "C" void kernel_launch(void* const* d_in, const int* in_sizes, int n_in,
                              void* d_out, int out_size)
{
    const float* x   = (const float*)d_in[0];
    const float* w1  = (const float*)d_in[1];
    const float* w2  = (const float*)d_in[2];
    const float* w3  = (const float*)d_in[3];
    const float* fcw = (const float*)d_in[4];
    int B = in_sizes[0] / 361;

    float* out  = (float*)d_out;
    float* logp = nullptr;
    float* feat = nullptr;
    if (out_size == 18 * B)      { logp = out; feat = out + (size_t)2 * B; }
    else if (out_size == 2 * B)  { logp = out; }
    else if (out_size == 16 * B) { feat = out; }
    else                         { logp = out; feat = out + (size_t)2 * B; }

    spd_precompute<<<1, 32>>>(w1, w2, w3);
    int blocks = (B + 15) / 16;
    spd_net_kernel<<<blocks, 256>>>(x, w1, w2, w3, fcw, logp, feat, B);
}

// round 16
// speedup vs baseline: 1.2245x; 1.2245x over previous
#include <cuda_runtime.h>
#include <math.h>

#define FULLMASK 0xffffffffu
#define EPS_REC 1e-4f

__device__ float g_C[361];     // eps * (w1 w1^T)^{-1}  (19x19, symmetric)
__device__ float g_W12[304];   // w1 * w2               (19x16)

// ---------------------------------------------------------------------------
// COLD one-sided Jacobi fallback (noinline; spills acceptable).
// ---------------------------------------------------------------------------
template<int N>
__device__ __noinline__ void jacobi_onesided(float (&g)[20], float (&v)[20],
                                             int lane, int max_sweeps)
{
    constexpr int M = N - 1;
    #pragma unroll
    for (int k = 0; k < N; ++k) v[k] = (lane == k) ? 1.0f : 0.0f;

    for (int sweep = 0; sweep < max_sweeps; ++sweep) {
        bool anyrot = false;
        for (int r = 0; r < M; ++r) {
            int partner;
            if (lane >= N)      partner = lane;
            else if (lane == M) partner = r;
            else if (lane == r) partner = M;
            else                partner = ((2 * r - lane) % M + M) % M;

            float pg[N];
            float a0 = 0.f, a1 = 0.f, d0 = 0.f, d1 = 0.f;
            #pragma unroll
            for (int k = 0; k < N; ++k) {
                pg[k] = __shfl_sync(FULLMASK, g[k], partner);
                if (k & 1) { a1 = fmaf(g[k], g[k], a1); d1 = fmaf(g[k], pg[k], d1); }
                else       { a0 = fmaf(g[k], g[k], a0); d0 = fmaf(g[k], pg[k], d0); }
            }
            float a = a0 + a1;
            float d = d0 + d1;
            float bb = __shfl_sync(FULLMASK, a, partner);
            bool  lower = lane < partner;
            float app = lower ? a  : bb;
            float aqq = lower ? bb : a;

            bool rot = (d * d > 1e-12f * app * aqq);
            anyrot |= rot;

            float dsafe = rot ? d : 1.0f;
            float tau = __fdividef(aqq - app, 2.0f * dsafe);
            float t   = __fdividef(copysignf(1.0f, tau),
                                   fabsf(tau) + __fsqrt_rn(fmaf(tau, tau, 1.0f)));
            float cc  = __frsqrt_rn(fmaf(t, t, 1.0f));
            float ss  = t * cc;
            if (!rot) { cc = 1.0f; ss = 0.0f; }
            float sl = lower ? -ss : ss;

            #pragma unroll
            for (int k = 0; k < N; ++k) {
                float pv = __shfl_sync(FULLMASK, v[k], partner);
                g[k] = fmaf(sl, pg[k], cc * g[k]);
                v[k] = fmaf(sl, pv,    cc * v[k]);
            }
        }
        if (!__any_sync(FULLMASK, anyrot)) break;
    }
}

// COLD: m += (eps - lambda_i) v_i v_i^T over deficient eigenpairs.
template<int N, int NREAL>
__device__ __noinline__ void reeig_correction(float (&m)[20], const float (&g)[20],
                                              const float (&v)[20], int lane)
{
    float lam = 0.f;
    #pragma unroll
    for (int k = 0; k < N; ++k) lam = fmaf(v[k], g[k], lam);

    bool defic = (lane < NREAL) && (lam < EPS_REC);
    unsigned mask = __ballot_sync(FULLMASK, defic);
    while (mask) {
        int i = __ffs(mask) - 1;
        mask &= mask - 1;
        float li   = __shfl_sync(FULLMASK, lam, i);
        float coef = EPS_REC - li;
        float vmy  = 0.f;
        float bv[N];
        #pragma unroll
        for (int k = 0; k < N; ++k) {
            bv[k] = __shfl_sync(FULLMASK, v[k], i);
            vmy   = (lane == k) ? bv[k] : vmy;
        }
        float cf = coef * vmy;
        #pragma unroll
        for (int k = 0; k < N; ++k) m[k] = fmaf(cf, bv[k], m[k]);
    }
}

// Vectorized dot of a 16B-aligned shared row with a register array.
template<int Q, int W>
__device__ __forceinline__ float dotv(const float* __restrict__ row,
                                      const float (&w)[W])
{
    const float4* r4 = (const float4*)row;
    float a0 = 0.f, a1 = 0.f, a2 = 0.f, a3 = 0.f;
    #pragma unroll
    for (int q = 0; q < Q; ++q) {
        float4 rv = r4[q];
        a0 = fmaf(rv.x, w[4 * q + 0], a0);
        a1 = fmaf(rv.y, w[4 * q + 1], a1);
        a2 = fmaf(rv.z, w[4 * q + 2], a2);
        a3 = fmaf(rv.w, w[4 * q + 3], a3);
    }
    return (a0 + a1) + (a2 + a3);
}

// COLD: single-matrix stage-1 GEMM M1 = w1^T X w1 (column `lane`).
// Reads w1 from GLOBAL (cold path only; no smem table kept for it).
__device__ __noinline__ void stage1_gemm(const float (*Sm)[20],
                                         const float* __restrict__ w1,
                                         int lane, float (&m)[20])
{
    int j = (lane < 19) ? lane : 0;
    float wc[20], t[20];
    #pragma unroll
    for (int k = 0; k < 19; ++k) wc[k] = __ldg(&w1[k * 19 + j]);
    wc[19] = 0.f;
    #pragma unroll
    for (int i = 0; i < 19; ++i) t[i] = dotv<5>(Sm[i], wc);
    t[19] = 0.f;
    #pragma unroll
    for (int i = 0; i < 19; ++i) {
        float acc = 0.f;
        #pragma unroll
        for (int k = 0; k < 19; ++k) acc = fmaf(__ldg(&w1[k * 19 + i]), t[k], acc);
        m[i] = (lane < 19) ? acc : 0.f;
    }
    m[19] = 0.f;
}

// Grouped Cholesky: two 16x16 per warp (g=lane>>4, j=lane&15). Sticky ok.
__device__ __forceinline__ bool chol16_grouped(const float (&m)[16], int lane)
{
    int base = lane & 16;
    int j    = lane & 15;
    float c[16];
    #pragma unroll
    for (int k = 0; k < 16; ++k) c[k] = (j == k) ? (m[k] - EPS_REC) : m[k];

    bool ok = true;
    #pragma unroll
    for (int k = 0; k < 16; ++k) {
        float ckk = __shfl_sync(FULLMASK, c[k], base + k);
        ok = ok && (ckk > 1e-12f);
        float gmul = c[k] * __fdividef(1.0f, fmaxf(ckk, 1e-12f));
        #pragma unroll
        for (int i = k + 1; i < 16; ++i) {
            float pk = __shfl_sync(FULLMASK, c[i], base + k);
            c[i] = fmaf(-pk, gmul, c[i]);
        }
    }
    return ok;
}

// Grouped 4x4 one-sided Jacobi: 8 independent 4-lane groups per warp.
__device__ __forceinline__ void jacobi4g(float (&g)[4], float (&v)[4],
                                         int lane, int max_sweeps)
{
    int j = lane & 3, base = lane & ~3;
    #pragma unroll
    for (int k = 0; k < 4; ++k) v[k] = (j == k) ? 1.0f : 0.0f;

    for (int sweep = 0; sweep < max_sweeps; ++sweep) {
        bool anyrot = false;
        #pragma unroll
        for (int r = 0; r < 3; ++r) {
            int p = (j == 3) ? r : (j == r) ? 3 : ((2 * r - j) % 3 + 3) % 3;
            int partner = base + p;

            float pg[4];
            float a = 0.f, d = 0.f;
            #pragma unroll
            for (int k = 0; k < 4; ++k) {
                pg[k] = __shfl_sync(FULLMASK, g[k], partner);
                a = fmaf(g[k], g[k], a);
                d = fmaf(g[k], pg[k], d);
            }
            float bb = __shfl_sync(FULLMASK, a, partner);
            bool  lower = j < p;
            float app = lower ? a  : bb;
            float aqq = lower ? bb : a;

            bool rot = (d * d > 1e-12f * app * aqq);
            anyrot |= rot;

            float dsafe = rot ? d : 1.0f;
            float tau = __fdividef(aqq - app, 2.0f * dsafe);
            float t   = __fdividef(copysignf(1.0f, tau),
                                   fabsf(tau) + __fsqrt_rn(fmaf(tau, tau, 1.0f)));
            float cc  = __frsqrt_rn(fmaf(t, t, 1.0f));
            float ss  = t * cc;
            if (!rot) { cc = 1.0f; ss = 0.0f; }
            float sl = lower ? -ss : ss;

            #pragma unroll
            for (int k = 0; k < 4; ++k) {
                float pv = __shfl_sync(FULLMASK, v[k], partner);
                g[k] = fmaf(sl, pg[k], cc * g[k]);
                v[k] = fmaf(sl, pv,    cc * v[k]);
            }
        }
        if (!__any_sync(FULLMASK, anyrot)) break;
    }
}

// ---------------------------------------------------------------------------
// Precompute (1 warp, SLIM — r12 version): C = eps*(w1 w1^T)^{-1} via
// LDL^T + L^{-1}; W12 = w1*w2. On numeric doubt: C := 1e30*I (all-cold, exact).
// ---------------------------------------------------------------------------
__global__ void spd_precompute(const float* __restrict__ w1,
                               const float* __restrict__ w2)
{
    __shared__ float s1[361], s2[304];
    int lane = threadIdx.x & 31;
    for (int i = lane; i < 361; i += 32) s1[i] = w1[i];
    for (int i = lane; i < 304; i += 32) s2[i] = w2[i];
    __syncwarp();

    int j = (lane < 19) ? lane : 0;

    // A = w1 w1^T, lane j owns column j
    float r[19], c[19];
    #pragma unroll
    for (int k = 0; k < 19; ++k) r[k] = s1[j * 19 + k];
    #pragma unroll
    for (int i = 0; i < 19; ++i) {
        float acc = 0.f;
        #pragma unroll
        for (int k = 0; k < 19; ++k) acc = fmaf(s1[i * 19 + k], r[k], acc);
        c[i] = acc;
    }

    // LDL^T with frozen finished columns
    bool ok = true;
    float invD[19];
    float myid = 1.0f;
    #pragma unroll
    for (int k = 0; k < 19; ++k) {
        float dk = __shfl_sync(FULLMASK, c[k], k);
        ok = ok && (dk > 1e-20f);
        float id = __fdividef(1.0f, fmaxf(dk, 1e-20f));
        invD[k] = id;
        if (k == j) myid = id;
        float gmul = (j > k) ? c[k] * id : 0.0f;
        #pragma unroll
        for (int i = k + 1; i < 19; ++i) {
            float pk = __shfl_sync(FULLMASK, c[i], k);
            c[i] = fmaf(-pk, gmul, c[i]);
        }
    }
    float l[19];
    #pragma unroll
    for (int i = 0; i < 19; ++i)
        l[i] = (i > j) ? c[i] * myid : ((i == j) ? 1.0f : 0.0f);

    // U = L^{-1}, column j by forward substitution
    float u[19];
    #pragma unroll
    for (int i = 0; i < 19; ++i) u[i] = (i == j) ? 1.0f : 0.0f;
    #pragma unroll
    for (int i = 1; i < 19; ++i) {
        float acc = 0.f;
        #pragma unroll
        for (int k = 0; k < i; ++k) {
            float Lik = __shfl_sync(FULLMASK, l[i], k);
            acc = fmaf(Lik, u[k], acc);
        }
        u[i] -= acc;
    }

    // C = eps * U^T D^{-1} U
    float z[19];
    #pragma unroll
    for (int m = 0; m < 19; ++m) z[m] = EPS_REC * invD[m] * u[m];
    #pragma unroll
    for (int a = 0; a < 19; ++a) {
        float acc = 0.f;
        #pragma unroll
        for (int m = 0; m < 19; ++m) {
            float Uma = __shfl_sync(FULLMASK, u[m], a);
            acc = fmaf(Uma, z[m], acc);
        }
        if (lane < 19) g_C[a * 19 + lane] = ok ? acc : ((a == lane) ? 1e30f : 0.0f);
    }

    // W12 = w1 * w2, column j16 per lane
    int j16 = (lane < 16) ? lane : 0;
    float rc[19];
    #pragma unroll
    for (int k = 0; k < 19; ++k) rc[k] = s2[k * 16 + j16];
    #pragma unroll
    for (int i = 0; i < 19; ++i) {
        float acc = 0.f;
        #pragma unroll
        for (int k = 0; k < 19; ++k) acc = fmaf(s1[i * 19 + k], rc[k], acc);
        if (lane < 16) g_W12[i * 16 + lane] = acc;
    }
}

// ---------------------------------------------------------------------------
// Main (r12 structure): 16 matrices / 256-thread block, 2 per warp.
// Dual interleaved chol19 on (X - C) replaces the stage-1 GEMM; fast Phase B
// computes M2 = W12^T X W12 from X; chol16 always confirms stage 2.
// Cold paths: exact stage-1 GEMM (global w1) + Jacobi fix.
// ---------------------------------------------------------------------------
__global__ void __launch_bounds__(256, 4)
spd_net_kernel(const float* __restrict__ x,
               const float* __restrict__ w1,
               const float* __restrict__ w2,
               const float* __restrict__ w3,
               const float* __restrict__ fcw,
               float* __restrict__ out_logp,
               float* __restrict__ out_feat,
               int B)
{
    __shared__ __align__(16) float sw2t[16][20];    // w2 cols (cold stage-2)
    __shared__ __align__(16) float sw12t[16][20];   // W12 cols (fast stage-2)
    __shared__ __align__(16) float sC[19][20];      // C rows, padded
    __shared__ __align__(16) float sw3t[4][20];
    __shared__ float sfc[32];
    __shared__ __align__(16) float S[16][21][20];   // 420-float stride/matrix

    int tid = threadIdx.x;
    for (int idx = tid; idx < 19 * 20; idx += 256) {
        int i = idx / 20, k = idx % 20;
        sC[i][k] = (k < 19) ? g_C[i * 19 + k] : 0.f;
    }
    for (int idx = tid; idx < 16 * 20; idx += 256) {
        int i = idx / 20, k = idx % 20;
        sw2t[i][k]  = (k < 19) ? w2[k * 16 + i] : 0.f;
        sw12t[i][k] = (k < 19) ? g_W12[k * 16 + i] : 0.f;
    }
    if (tid < 80) {
        int i = tid / 20, k = tid % 20;
        sw3t[i][k] = (k < 16) ? w3[k * 4 + i] : 0.f;
    }
    if (tid < 32) sfc[tid] = fcw[tid];
    __syncthreads();

    int warp = tid >> 5, lane = tid & 31;
    int blockBase = blockIdx.x * 16;
    int qA = 2 * warp, qBm = qA + 1;
    int bA = blockBase + qA, bB = blockBase + qBm;
    float (*SmA)[20] = S[qA];
    float (*SmB)[20] = S[qBm];

    if (bA < B) {
        const float* xa = x + (size_t)bA * 361;
        for (int i = lane; i < 361; i += 32) SmA[i / 19][i % 19] = xa[i];
    }
    if (bB < B) {
        const float* xb = x + (size_t)bB * 361;
        for (int i = lane; i < 361; i += 32) SmB[i / 19][i % 19] = xb[i];
    }
    if (lane < 19) { SmA[lane][19] = 0.f; SmB[lane][19] = 0.f; }
    __syncwarp();

    int j19 = (lane < 19) ? lane : 0;

    // ======== Stage-1 PD test: dual interleaved chol19 on (X - C) ========
    bool okA = true, okB = true;
    {
        float cA[19], cB[19];
        #pragma unroll
        for (int k = 0; k < 19; ++k) {
            float ck = sC[k][j19];
            cA[k] = SmA[k][j19] - ck;
            cB[k] = SmB[k][j19] - ck;
        }
        #pragma unroll
        for (int k = 0; k < 19; ++k) {
            float pA = __shfl_sync(FULLMASK, cA[k], k);
            float pB = __shfl_sync(FULLMASK, cB[k], k);
            okA = okA && (pA > 1e-12f);
            okB = okB && (pB > 1e-12f);
            float gA = cA[k] * __fdividef(1.0f, fmaxf(pA, 1e-12f));
            float gB = cB[k] * __fdividef(1.0f, fmaxf(pB, 1e-12f));
            #pragma unroll
            for (int i = k + 1; i < 19; ++i) {
                float fA = __shfl_sync(FULLMASK, cA[i], k);
                float fB = __shfl_sync(FULLMASK, cB[i], k);
                cA[i] = fmaf(-fA, gA, cA[i]);
                cB[i] = fmaf(-fB, gB, cB[i]);
            }
        }
    }

    // ======== Cold stage-1: compute M1, ReEig, overwrite X with Y1 ========
    bool badA = !okA && (bA < B);
    bool badB = !okB && (bB < B);
    if (badA || badB) {
        #pragma unroll 1
        for (int rr = 0; rr < 2; ++rr) {
            bool bad = rr ? badB : badA;
            if (bad) {
                float (*Sm)[20] = rr ? SmB : SmA;
                float m[20], g[20], v[20];
                stage1_gemm(Sm, w1, lane, m);
                #pragma unroll
                for (int k = 0; k < 20; ++k) g[k] = m[k];
                jacobi_onesided<20>(g, v, lane, 12);
                reeig_correction<20, 19>(m, g, v, lane);
                __syncwarp();
                if (lane < 19) {
                    #pragma unroll
                    for (int k = 0; k < 19; ++k) Sm[k][lane] = m[k];  // Y1
                }
            }
            __syncwarp();
        }
    }
    __syncwarp();

    // ======== Phase B: M2 from rows 0-18 with W12 (fast) or w2 (cold) ======
    int gB2 = lane >> 4;
    int jB  = lane & 15;
    float (*SmP)[20] = S[2 * warp + gB2];
    bool fastP = gB2 ? okB : okA;
    const float (*wt)[20] = fastP ? sw12t : sw2t;

    float m16[16];
    {
        float wc[20], t[20];
        #pragma unroll
        for (int q = 0; q < 5; ++q)
            *(float4*)&wc[4 * q] = *(const float4*)&wt[jB][4 * q];
        #pragma unroll
        for (int kk = 0; kk < 19; ++kk) t[kk] = dotv<5>(SmP[kk], wc);
        t[19] = 0.f;
        #pragma unroll
        for (int i = 0; i < 16; ++i) m16[i] = dotv<5>(wt[i], t);
    }

    bool okP = chol16_grouped(m16, lane);
    __syncwarp();                                   // all reads of rows 0-18 done
    #pragma unroll
    for (int k = 0; k < 16; ++k) SmP[k][jB] = m16[k];   // Y2 over rows 0-15
    __syncwarp();

    if (!__all_sync(FULLMASK, okP)) {               // COLD stage-2 fix
        #pragma unroll 1
        for (int rr = 0; rr < 2; ++rr) {
            int qq = 2 * warp + rr;
            bool qok = __shfl_sync(FULLMASK, okP, rr * 16) || (blockBase + qq >= B);
            if (!qok) {
                float mm[20], g[20], v[20];
                #pragma unroll
                for (int k = 0; k < 16; ++k)
                    mm[k] = (lane < 16) ? S[qq][k][lane] : 0.f;
                #pragma unroll
                for (int k = 16; k < 20; ++k) mm[k] = 0.f;
                #pragma unroll
                for (int k = 0; k < 20; ++k) g[k] = mm[k];
                jacobi_onesided<16>(g, v, lane, 12);
                reeig_correction<16, 16>(mm, g, v, lane);
                __syncwarp();
                if (lane < 16) {
                    #pragma unroll
                    for (int k = 0; k < 16; ++k) S[qq][k][lane] = mm[k];
                }
            }
            __syncwarp();
        }
    }

    __syncthreads();                                // handoff to Phase C

    // ======== Phase C (warps 0-1 only): 8 matrices per warp ========
    if (warp >= 2) return;

    int jC = lane & 3;
    int gC = lane >> 2;
    int qC = warp * 8 + gC;
    int bC = blockBase + qC;
    float (*SmC)[20] = S[qC];

    float m4[4];
    {
        float wc[16], t[16];
        #pragma unroll
        for (int q = 0; q < 4; ++q)
            *(float4*)&wc[4 * q] = *(const float4*)&sw3t[jC][4 * q];
        #pragma unroll
        for (int kk = 0; kk < 16; ++kk) t[kk] = dotv<4>(SmC[kk], wc);
        #pragma unroll
        for (int i = 0; i < 4; ++i) m4[i] = dotv<4>(sw3t[i], t);
    }

    float g4[4], v4[4];
    #pragma unroll
    for (int k = 0; k < 4; ++k) g4[k] = m4[k];
    jacobi4g(g4, v4, lane, 8);

    float lam = 0.f;
    #pragma unroll
    for (int k = 0; k < 4; ++k) lam = fmaf(v4[k], g4[k], lam);
    float ll = logf(fmaxf(lam, 1e-30f));

    int baseC = lane & ~3;
    float c3[4] = {0.f, 0.f, 0.f, 0.f};
    #pragma unroll
    for (int mm = 0; mm < 4; ++mm) {
        float llm = __shfl_sync(FULLMASK, ll,    baseC + mm);
        float bv0 = __shfl_sync(FULLMASK, v4[0], baseC + mm);
        float bv1 = __shfl_sync(FULLMASK, v4[1], baseC + mm);
        float bv2 = __shfl_sync(FULLMASK, v4[2], baseC + mm);
        float bv3 = __shfl_sync(FULLMASK, v4[3], baseC + mm);
        float vmj = (jC == 0) ? bv0 : (jC == 1) ? bv1 : (jC == 2) ? bv2 : bv3;
        float cf  = llm * vmj;
        c3[0] = fmaf(cf, bv0, c3[0]);
        c3[1] = fmaf(cf, bv1, c3[1]);
        c3[2] = fmaf(cf, bv2, c3[2]);
        c3[3] = fmaf(cf, bv3, c3[3]);
    }

    bool inRange = (bC < B);

    if (out_feat && inRange) {
        #pragma unroll
        for (int i = 0; i < 4; ++i)
            out_feat[(size_t)bC * 16 + i * 4 + jC] = c3[i];
    }

    if (out_logp) {
        float p0 = 0.f, p1 = 0.f;
        #pragma unroll
        for (int i = 0; i < 4; ++i) {
            int f = i * 4 + jC;
            p0 = fmaf(c3[i], sfc[f * 2 + 0], p0);
            p1 = fmaf(c3[i], sfc[f * 2 + 1], p1);
        }
        p0 += __shfl_xor_sync(FULLMASK, p0, 1);
        p0 += __shfl_xor_sync(FULLMASK, p0, 2);
        p1 += __shfl_xor_sync(FULLMASK, p1, 1);
        p1 += __shfl_xor_sync(FULLMASK, p1, 2);
        if (inRange && jC == 0) {
            float mx  = fmaxf(p0, p1);
            float lse = mx + logf(expf(p0 - mx) + expf(p1 - mx));
            out_logp[(size_t)bC * 2 + 0] = p0 - lse;
            out_logp[(size_t)bC * 2 + 1] = p1 - lse;
        }
    }
}

extern "C" void kernel_launch(void* const* d_in, const int* in_sizes, int n_in,
                              void* d_out, int out_size)
{
    const float* x   = (const float*)d_in[0];
    const float* w1  = (const float*)d_in[1];
    const float* w2  = (const float*)d_in[2];
    const float* w3  = (const float*)d_in[3];
    const float* fcw = (const float*)d_in[4];
    int B = in_sizes[0] / 361;

    float* out  = (float*)d_out;
    float* logp = nullptr;
    float* feat = nullptr;
    if (out_size == 18 * B)      { logp = out; feat = out + (size_t)2 * B; }
    else if (out_size == 2 * B)  { logp = out; }
    else if (out_size == 16 * B) { feat = out; }
    else                         { logp = out; feat = out + (size_t)2 * B; }

    spd_precompute<<<1, 32>>>(w1, w2);
    int blocks = (B + 15) / 16;
    spd_net_kernel<<<blocks, 256>>>(x, w1, w2, w3, fcw, logp, feat, B);
}